// round 9
// baseline (speedup 1.0000x reference)
#include <cuda_runtime.h>
#include <cuda_bf16.h>
#include <cstdint>

#define N_NODES  100000
#define N_EDGES  600000
#define N_GRAPHS 2000
#define HID      128
#define LAYERS   6
#define SA       136               // bf16 row stride in smem
#define NODES_PT 64                // nodes per tile
#define NT       ((N_NODES + NODES_PT - 1) / NODES_PT)   // 1563
#define NBLK     148
#define NTHREADS 384               // 8 consumer warps + 4 producer warps
#define SCAN_B   1024
#define SCAN_NB  ((N_NODES + SCAN_B - 1) / SCAN_B)

// named barrier IDs
#define BAR_FULL0   1
#define BAR_FULL1   2
#define BAR_EMPTY0  3
#define BAR_EMPTY1  4
#define BAR_CONS    5

// ---------------------------------------------------------------------------
// Persistent scratch (allocation-free). Ping-pong x buffers: layer l reads
// buf[l&1], writes buf[1-(l&1)] -> producers never race with consumers.
// ---------------------------------------------------------------------------
__device__ float g_xa[(size_t)N_NODES * HID];
__device__ float g_xb[(size_t)N_NODES * HID];
__device__ __align__(16) __nv_bfloat16 g_wt[(size_t)2 * 2 * LAYERS * HID * SA];
// CSR scratch
__device__ int g_deg[N_NODES];
__device__ int g_rowstart[N_NODES + 1];
__device__ int g_cursor[N_NODES];
__device__ int g_blocksum[SCAN_NB];
__device__ int g_csr[N_EDGES];

// ---------------------------------------------------------------------------
// helpers
// ---------------------------------------------------------------------------
__device__ __forceinline__ uint32_t smem_u32(const void* p) {
    uint32_t a;
    asm("{ .reg .u64 t; cvta.to.shared.u64 t, %1; cvt.u32.u64 %0, t; }"
        : "=r"(a) : "l"(p));
    return a;
}
__device__ __forceinline__ void ldm_x4(uint32_t (&r)[4], uint32_t addr) {
    asm volatile("ldmatrix.sync.aligned.m8n8.x4.shared.b16 {%0,%1,%2,%3}, [%4];"
                 : "=r"(r[0]), "=r"(r[1]), "=r"(r[2]), "=r"(r[3]) : "r"(addr));
}
__device__ __forceinline__ void mma16816(float (&d)[4], const uint32_t (&a)[4],
                                         uint32_t b0, uint32_t b1) {
    asm volatile(
        "mma.sync.aligned.m16n8k16.row.col.f32.bf16.bf16.f32 "
        "{%0,%1,%2,%3}, {%4,%5,%6,%7}, {%8,%9}, {%0,%1,%2,%3};"
        : "+f"(d[0]), "+f"(d[1]), "+f"(d[2]), "+f"(d[3])
        : "r"(a[0]), "r"(a[1]), "r"(a[2]), "r"(a[3]), "r"(b0), "r"(b1));
}
__device__ __forceinline__ uint32_t pk(__nv_bfloat16 a, __nv_bfloat16 b) {
    return (uint32_t)__bfloat16_as_ushort(a) |
           ((uint32_t)__bfloat16_as_ushort(b) << 16);
}
#define BAR_SYNC(id, cnt) \
    asm volatile("bar.sync %0, %1;" :: "r"(id), "r"(cnt) : "memory")
#define BAR_ARRIVE(id, cnt) \
    asm volatile("bar.arrive %0, %1;" :: "r"(id), "r"(cnt) : "memory")

// ---------------------------------------------------------------------------
// Embedding lookup -> g_xa
// ---------------------------------------------------------------------------
__global__ void embed_kernel(const int* __restrict__ tok,
                             const float* __restrict__ emb) {
    int i = blockIdx.x * blockDim.x + threadIdx.x;
    if (i >= N_NODES * 32) return;
    int node = i >> 5, d = i & 31;
    ((float4*)g_xa)[i] = ((const float4*)emb)[tok[node] * 32 + d];
}

// ---------------------------------------------------------------------------
// CSR build
// ---------------------------------------------------------------------------
__global__ void k_zero() {
    int i = blockIdx.x * blockDim.x + threadIdx.x;
    if (i < N_NODES) g_deg[i] = 0;
}
__global__ void k_hist(const int* __restrict__ ei) {
    int i = blockIdx.x * blockDim.x + threadIdx.x;
    if (i < N_EDGES) atomicAdd(&g_deg[ei[N_EDGES + i]], 1);
}
__global__ void k_scan1() {
    __shared__ int sm[SCAN_B];
    int tid = threadIdx.x;
    int i = blockIdx.x * SCAN_B + tid;
    int v = (i < N_NODES) ? g_deg[i] : 0;
    sm[tid] = v;
    __syncthreads();
#pragma unroll
    for (int o = 1; o < SCAN_B; o <<= 1) {
        int t = (tid >= o) ? sm[tid - o] : 0;
        __syncthreads();
        sm[tid] += t;
        __syncthreads();
    }
    if (i < N_NODES) g_rowstart[i] = sm[tid] - v;
    if (tid == SCAN_B - 1) g_blocksum[blockIdx.x] = sm[tid];
}
__global__ void k_scan2() {
    if (threadIdx.x == 0) {
        int run = 0;
        for (int b = 0; b < SCAN_NB; b++) {
            int t = g_blocksum[b];
            g_blocksum[b] = run;
            run += t;
        }
        g_rowstart[N_NODES] = run;
    }
}
__global__ void k_scan3() {
    int i = blockIdx.x * blockDim.x + threadIdx.x;
    if (i < N_NODES) {
        int r = g_rowstart[i] + g_blocksum[i / SCAN_B];
        g_rowstart[i] = r;
        g_cursor[i] = r;
    }
}
__global__ void k_fill(const int* __restrict__ ei) {
    int i = blockIdx.x * blockDim.x + threadIdx.x;
    if (i < N_EDGES) {
        int dst = ei[N_EDGES + i];
        g_csr[atomicAdd(&g_cursor[dst], 1)] = ei[i];
    }
}

// ---------------------------------------------------------------------------
// Weight prep: split W[k][c] -> transposed hi/lo images Wt[c][k], stride SA.
// ---------------------------------------------------------------------------
__global__ void prep_w(const float* __restrict__ W1, const float* __restrict__ W2) {
    int i = blockIdx.x * blockDim.x + threadIdx.x;
    if (i >= 2 * LAYERS * HID * HID) return;
    int which = i / (LAYERS * HID * HID);
    int r = i % (LAYERS * HID * HID);
    int l = r / (HID * HID);
    int kc = r % (HID * HID);
    int k = kc / HID, c = kc % HID;
    const float* W = which ? W2 : W1;
    float v = W[(size_t)l * HID * HID + k * HID + c];
    __nv_bfloat16 hi = __float2bfloat16(v);
    __nv_bfloat16 lo = __float2bfloat16(v - __bfloat162float(hi));
    size_t img = (size_t)which * LAYERS + l;
    size_t o = img * HID * SA + (size_t)c * SA + k;
    g_wt[o] = hi;
    g_wt[(size_t)2 * LAYERS * HID * SA + o] = lo;
}

// ---------------------------------------------------------------------------
// Fused persistent gather + GIN MLP, warp-specialized.
// warps 0-7: GEMM consumers.  warps 8-11: gather producers (read x_in).
// Consumers write x_out (different buffer) -> no global race.
// ---------------------------------------------------------------------------
#define WTILE_B   (HID * SA * 2)          // 34816
#define AHALF_B   (NODES_PT * SA * 2)     // 17408
#define ABUF_B    (2 * AHALF_B)           // 34816
#define SMEM_BYTES (4 * WTILE_B + 2 * ABUF_B)  // 208896

// 3-product split GEMM over a 32x32 warp tile.
__device__ __forceinline__ void gemm_warp(
    uint32_t aAhi, uint32_t aAlo, uint32_t aWh, uint32_t aWl,
    int m0, int n0, int arow_off, int akoff, int brow_off, int bkoff,
    float (&acc)[2][4][4])
{
#pragma unroll
    for (int kb = 0; kb < HID; kb += 16) {
        uint32_t ah[2][4], al[2][4];
#pragma unroll
        for (int s = 0; s < 2; s++) {
            uint32_t ro = (uint32_t)((m0 + s * 16 + arow_off) * SA + kb + akoff) * 2;
            ldm_x4(ah[s], aAhi + ro);
            ldm_x4(al[s], aAlo + ro);
        }
#pragma unroll
        for (int nb = 0; nb < 2; nb++) {
            uint32_t bh[4], bl[4];
            uint32_t ro = (uint32_t)((n0 + nb * 16 + brow_off) * SA + kb + bkoff) * 2;
            ldm_x4(bh, aWh + ro);
            ldm_x4(bl, aWl + ro);
#pragma unroll
            for (int s = 0; s < 2; s++) {
                mma16816(acc[s][2 * nb],     ah[s], bh[0], bh[1]);
                mma16816(acc[s][2 * nb],     ah[s], bl[0], bl[1]);
                mma16816(acc[s][2 * nb],     al[s], bh[0], bh[1]);
                mma16816(acc[s][2 * nb + 1], ah[s], bh[2], bh[3]);
                mma16816(acc[s][2 * nb + 1], ah[s], bl[2], bl[3]);
                mma16816(acc[s][2 * nb + 1], al[s], bh[2], bh[3]);
            }
        }
    }
}

__global__ void __launch_bounds__(NTHREADS, 1) mlp_fused(
    const float* __restrict__ b1, const float* __restrict__ b2, int l,
    int parity)   // parity 0: read g_xa write g_xb; 1: read g_xb write g_xa
{
    extern __shared__ __align__(16) char S[];
    uint32_t base = smem_u32(S);
    uint32_t aW1h = base, aW1l = base + WTILE_B;
    uint32_t aW2h = base + 2 * WTILE_B, aW2l = base + 3 * WTILE_B;
    uint32_t aBuf[2] = { base + 4 * WTILE_B, base + 4 * WTILE_B + ABUF_B };
    char* pBuf[2] = { S + 4 * WTILE_B, S + 4 * WTILE_B + ABUF_B };

    const float* xin = parity ? g_xb : g_xa;
    float*       xout = parity ? g_xa : g_xb;

    int tid = threadIdx.x, warp = tid >> 5, lane = tid & 31;
    int bid = blockIdx.x;

    // ---- stage all weights once (all 384 threads) ----
    {
        const size_t istr = (size_t)HID * SA;
        const size_t lstr = (size_t)2 * LAYERS * HID * SA;
        const float4* srcs[4] = {
            (const float4*)(g_wt + (size_t)l * istr),
            (const float4*)(g_wt + lstr + (size_t)l * istr),
            (const float4*)(g_wt + (size_t)(LAYERS + l) * istr),
            (const float4*)(g_wt + lstr + (size_t)(LAYERS + l) * istr) };
#pragma unroll
        for (int q = 0; q < 4; q++) {
            float4* d = (float4*)(S + q * WTILE_B);
            for (int i = tid; i < WTILE_B / 16; i += NTHREADS) d[i] = srcs[q][i];
        }
    }
    __syncthreads();

    if (warp >= 8) {
        // ================= PRODUCER: gather xin[n] + sum xin[csr] ===========
        int pw = warp - 8;                    // 0..3
        const float4* x4 = (const float4*)xin;
        int it = 0;
        for (int t = bid; t < NT; t += NBLK, it++) {
            int s = it & 1;
            if (it >= 2) BAR_SYNC(BAR_EMPTY0 + s, NTHREADS);
            int node0 = t * NODES_PT;
            char* pA = pBuf[s];
#pragma unroll 2
            for (int i = pw; i < NODES_PT; i += 4) {
                int n = node0 + i;
                float4 v = make_float4(0.f, 0.f, 0.f, 0.f);
                if (n < N_NODES) {
                    v = x4[(size_t)n * 32 + lane];
                    int e0 = __ldg(g_rowstart + n), e1 = __ldg(g_rowstart + n + 1);
                    for (int e = e0; e < e1; e++) {
                        int src = __ldg(g_csr + e);
                        float4 u = x4[(size_t)src * 32 + lane];
                        v.x += u.x; v.y += u.y; v.z += u.z; v.w += u.w;
                    }
                }
                __nv_bfloat16 h0 = __float2bfloat16(v.x), h1 = __float2bfloat16(v.y);
                __nv_bfloat16 h2 = __float2bfloat16(v.z), h3 = __float2bfloat16(v.w);
                __nv_bfloat16 q0 = __float2bfloat16(v.x - __bfloat162float(h0));
                __nv_bfloat16 q1 = __float2bfloat16(v.y - __bfloat162float(h1));
                __nv_bfloat16 q2 = __float2bfloat16(v.z - __bfloat162float(h2));
                __nv_bfloat16 q3 = __float2bfloat16(v.w - __bfloat162float(h3));
                uint32_t off = (uint32_t)(i * SA + lane * 4) * 2;
                *(uint2*)(pA + off) = make_uint2(pk(h0, h1), pk(h2, h3));
                *(uint2*)(pA + AHALF_B + off) = make_uint2(pk(q0, q1), pk(q2, q3));
            }
            BAR_ARRIVE(BAR_FULL0 + s, NTHREADS);
        }
    } else {
        // ================= CONSUMER: 2 GEMMs + epilogues ====================
        int m0 = (warp >> 2) * 32;
        int n0 = (warp & 3) * 32;
        int g = lane >> 3;
        int arow_off = (lane & 7) + ((g & 1) << 3);
        int akoff    = (g >> 1) << 3;
        int brow_off = (lane & 7) + ((g >> 1) << 3);
        int bkoff    = (g & 1) << 3;

        float b1v[4][2], b2v[4][2];
#pragma unroll
        for (int j = 0; j < 4; j++) {
            int col = n0 + j * 8 + (lane & 3) * 2;
            b1v[j][0] = __ldg(b1 + col); b1v[j][1] = __ldg(b1 + col + 1);
            b2v[j][0] = __ldg(b2 + col); b2v[j][1] = __ldg(b2 + col + 1);
        }

        int it = 0;
        for (int t = bid; t < NT; t += NBLK, it++) {
            int s = it & 1;
            int node0 = t * NODES_PT;
            BAR_SYNC(BAR_FULL0 + s, NTHREADS);   // wait A tile

            uint32_t aAhi = aBuf[s], aAlo = aBuf[s] + AHALF_B;
            char* pA = pBuf[s];

            float acc[2][4][4];
#pragma unroll
            for (int q = 0; q < 2; q++)
#pragma unroll
                for (int j = 0; j < 4; j++)
#pragma unroll
                    for (int c = 0; c < 4; c++) acc[q][j][c] = 0.f;

            gemm_warp(aAhi, aAlo, aW1h, aW1l, m0, n0,
                      arow_off, akoff, brow_off, bkoff, acc);
            BAR_SYNC(BAR_CONS, 256);   // all consumers done reading A

            // epilogue 1: h = relu(acc + b1) -> overwrite A buf (hi/lo)
            {
                int r0 = m0 + (lane >> 2);
#pragma unroll
                for (int j = 0; j < 4; j++) {
                    int col = n0 + j * 8 + (lane & 3) * 2;
#pragma unroll
                    for (int q = 0; q < 2; q++) {
                        int rA = r0 + q * 16, rB = rA + 8;
                        float v0 = fmaxf(acc[q][j][0] + b1v[j][0], 0.f);
                        float v1 = fmaxf(acc[q][j][1] + b1v[j][1], 0.f);
                        float v2 = fmaxf(acc[q][j][2] + b1v[j][0], 0.f);
                        float v3 = fmaxf(acc[q][j][3] + b1v[j][1], 0.f);
                        __nv_bfloat16 h0 = __float2bfloat16(v0), h1 = __float2bfloat16(v1);
                        __nv_bfloat16 h2 = __float2bfloat16(v2), h3 = __float2bfloat16(v3);
                        __nv_bfloat16 p0 = __float2bfloat16(v0 - __bfloat162float(h0));
                        __nv_bfloat16 p1 = __float2bfloat16(v1 - __bfloat162float(h1));
                        __nv_bfloat16 p2 = __float2bfloat16(v2 - __bfloat162float(h2));
                        __nv_bfloat16 p3 = __float2bfloat16(v3 - __bfloat162float(h3));
                        uint32_t oA = (uint32_t)(rA * SA + col) * 2;
                        uint32_t oB = (uint32_t)(rB * SA + col) * 2;
                        *(uint32_t*)(pA + oA) = pk(h0, h1);
                        *(uint32_t*)(pA + AHALF_B + oA) = pk(p0, p1);
                        *(uint32_t*)(pA + oB) = pk(h2, h3);
                        *(uint32_t*)(pA + AHALF_B + oB) = pk(p2, p3);
                    }
                }
            }
            BAR_SYNC(BAR_CONS, 256);   // H complete

#pragma unroll
            for (int q = 0; q < 2; q++)
#pragma unroll
                for (int j = 0; j < 4; j++)
#pragma unroll
                    for (int c = 0; c < 4; c++) acc[q][j][c] = 0.f;

            gemm_warp(aAhi, aAlo, aW2h, aW2l, m0, n0,
                      arow_off, akoff, brow_off, bkoff, acc);
            BAR_ARRIVE(BAR_EMPTY0 + s, NTHREADS);   // buffer free for producer

            // epilogue 2: relu(acc + b2) -> xout
            {
                int r0 = m0 + (lane >> 2);
#pragma unroll
                for (int j = 0; j < 4; j++) {
                    int col = n0 + j * 8 + (lane & 3) * 2;
#pragma unroll
                    for (int q = 0; q < 2; q++) {
                        int rA = r0 + q * 16, rB = rA + 8;
                        int gA = node0 + rA, gB = node0 + rB;
                        if (gA < N_NODES) {
                            float2 v = make_float2(fmaxf(acc[q][j][0] + b2v[j][0], 0.f),
                                                   fmaxf(acc[q][j][1] + b2v[j][1], 0.f));
                            *(float2*)(xout + (size_t)gA * HID + col) = v;
                        }
                        if (gB < N_NODES) {
                            float2 v = make_float2(fmaxf(acc[q][j][2] + b2v[j][0], 0.f),
                                                   fmaxf(acc[q][j][3] + b2v[j][1], 0.f));
                            *(float2*)(xout + (size_t)gB * HID + col) = v;
                        }
                    }
                }
            }
        }
    }
}

// ---------------------------------------------------------------------------
// Global mean pool (reads g_xa: LAYERS is even so final x lands there)
// ---------------------------------------------------------------------------
__global__ void pool_kernel(const int* __restrict__ batch,
                            float* __restrict__ out) {
    int g = blockIdx.x;
    __shared__ int s_range[2];
    if (threadIdx.x == 0) {
        int lo = 0, hi = N_NODES;
        while (lo < hi) { int m = (lo + hi) >> 1; if (batch[m] < g) lo = m + 1; else hi = m; }
        s_range[0] = lo;
        lo = 0; hi = N_NODES;
        while (lo < hi) { int m = (lo + hi) >> 1; if (batch[m] < g + 1) lo = m + 1; else hi = m; }
        s_range[1] = lo;
    }
    __syncthreads();
    int start = s_range[0], end = s_range[1];
    float sum = 0.f;
    for (int n = start; n < end; n++)
        sum += g_xa[(size_t)n * HID + threadIdx.x];
    float cnt = (float)(end - start);
    out[g * HID + threadIdx.x] = sum / fmaxf(cnt, 1.0f);
}

// ---------------------------------------------------------------------------
// Inputs: x_tokens, edge_index, batch, emb, W1, b1, W2, b2
// ---------------------------------------------------------------------------
extern "C" void kernel_launch(void* const* d_in, const int* in_sizes, int n_in,
                              void* d_out, int out_size) {
    const int*   tok   = (const int*)  d_in[0];
    const int*   ei    = (const int*)  d_in[1];
    const int*   batch = (const int*)  d_in[2];
    const float* emb   = (const float*)d_in[3];
    const float* W1    = (const float*)d_in[4];
    const float* b1    = (const float*)d_in[5];
    const float* W2    = (const float*)d_in[6];
    const float* b2    = (const float*)d_in[7];
    float* out = (float*)d_out;

    cudaFuncSetAttribute(mlp_fused, cudaFuncAttributeMaxDynamicSharedMemorySize,
                         SMEM_BYTES);

    prep_w<<<(2 * LAYERS * HID * HID + 255) / 256, 256>>>(W1, W2);
    embed_kernel<<<(N_NODES * 32 + 255) / 256, 256>>>(tok, emb);

    k_zero <<<(N_NODES + 255) / 256, 256>>>();
    k_hist <<<(N_EDGES + 255) / 256, 256>>>(ei);
    k_scan1<<<SCAN_NB, SCAN_B>>>();
    k_scan2<<<1, 32>>>();
    k_scan3<<<(N_NODES + 255) / 256, 256>>>();
    k_fill <<<(N_EDGES + 255) / 256, 256>>>(ei);

    for (int l = 0; l < LAYERS; l++) {
        mlp_fused<<<NBLK, NTHREADS, SMEM_BYTES>>>(
            b1 + (size_t)l * HID, b2 + (size_t)l * HID, l, l & 1);
    }

    pool_kernel<<<N_GRAPHS, HID>>>(batch, out);
}